// round 2
// baseline (speedup 1.0000x reference)
#include <cuda_runtime.h>
#include <cuda_bf16.h>

// Sampler_32865089749571: the full temperature + top-p/top-k + softmax + argmax
// pipeline reduces to a row-wise argmax of the raw logits:
//  - rank-0 of the descending sort is never masked (top-k mask: rank>=50;
//    top-p mask: cumsum-excl-self > p, which is 0 at rank 0),
//  - temperature scaling (T>0) and softmax are monotone.
// So argmax(probs) == argmax(logits), with matching lowest-index tie-breaking.
//
// [256, 128000] fp32 -> [256, 1] (output stored as float — bench compares in f32).
// Pure HBM-bound: 131 MB read -> ~18 us at ~7 TB/s achieved.

#define VOCAB 128000
#define BATCH 256
#define NT    512
#define NWARP (NT / 32)

__global__ __launch_bounds__(NT, 2)
void rowwise_argmax_kernel(const float* __restrict__ logits,
                           float* __restrict__ out) {
    const int row = blockIdx.x;
    const float4* __restrict__ p =
        reinterpret_cast<const float4*>(logits) + (size_t)row * (VOCAB / 4);

    float best = -__int_as_float(0x7f800000);  // -inf
    int bidx = 0;

    // Grid-stride over the row in float4 units. Per-thread indices ascend, so
    // strict '>' keeps the lowest index on ties within a thread.
    #pragma unroll 4
    for (int i = threadIdx.x; i < VOCAB / 4; i += NT) {
        const float4 v = p[i];
        const int base = i * 4;
        if (v.x > best) { best = v.x; bidx = base;     }
        if (v.y > best) { best = v.y; bidx = base + 1; }
        if (v.z > best) { best = v.z; bidx = base + 2; }
        if (v.w > best) { best = v.w; bidx = base + 3; }
    }

    // Warp reduction: max value, ties -> smaller index.
    const unsigned full = 0xffffffffu;
    #pragma unroll
    for (int off = 16; off; off >>= 1) {
        const float ov = __shfl_down_sync(full, best, off);
        const int   oi = __shfl_down_sync(full, bidx, off);
        if (ov > best || (ov == best && oi < bidx)) { best = ov; bidx = oi; }
    }

    __shared__ float sv[NWARP];
    __shared__ int   si[NWARP];
    const int wid = threadIdx.x >> 5;
    const int lid = threadIdx.x & 31;
    if (lid == 0) { sv[wid] = best; si[wid] = bidx; }
    __syncthreads();

    if (wid == 0) {
        best = (lid < NWARP) ? sv[lid] : -__int_as_float(0x7f800000);
        bidx = (lid < NWARP) ? si[lid] : 0x7fffffff;
        #pragma unroll
        for (int off = NWARP / 2; off; off >>= 1) {
            const float ov = __shfl_down_sync(full, best, off);
            const int   oi = __shfl_down_sync(full, bidx, off);
            if (ov > best || (ov == best && oi < bidx)) { best = ov; bidx = oi; }
        }
        if (lid == 0) out[row] = (float)bidx;
    }
}

extern "C" void kernel_launch(void* const* d_in, const int* in_sizes, int n_in,
                              void* d_out, int out_size) {
    const float* logits = (const float*)d_in[0];
    float* out = (float*)d_out;
    rowwise_argmax_kernel<<<BATCH, NT>>>(logits, out);
}